// round 3
// baseline (speedup 1.0000x reference)
#include <cuda_runtime.h>
#include <stdint.h>

#define N_NODES 100000
#define E_EDGES 1600000
#define HID 64

// ---------------- scratch (no allocation allowed) ----------------
__device__ float g_bufA[N_NODES * HID];   // h_lin
__device__ float g_bufB[N_NODES * HID];   // agg
__device__ float g_deg[N_NODES];
__device__ float g_dinv[N_NODES];
__device__ int   g_src[E_EDGES];
__device__ int   g_dst[E_EDGES];
__device__ float g_norm[E_EDGES];
__device__ int   g_is64;                  // 1 if edge_index is int64, 0 if int32

__device__ __forceinline__ float lrelu1(float v) {
    return fmaxf(v, 0.f) + 0.01f * fminf(v, 0.f);
}

// ---------------- dtype detection (runs every launch; deterministic) ------
// If the buffer holds int64 values in [0, N), every hi-word is 0. If it holds
// int32 indices, the "hi-word" slots are themselves random indices and are
// almost surely nonzero somewhere in 2048 samples.
__global__ void k_detect(const unsigned int* __restrict__ u32buf) {
    __shared__ unsigned int s_or[256];
    unsigned int acc = 0;
    for (int i = threadIdx.x; i < 2048; i += 256)
        acc |= u32buf[2 * i + 1];          // hi word of candidate int64 #i
    s_or[threadIdx.x] = acc;
    __syncthreads();
    for (int s = 128; s > 0; s >>= 1) {
        if (threadIdx.x < s) s_or[threadIdx.x] |= s_or[threadIdx.x + s];
        __syncthreads();
    }
    if (threadIdx.x == 0) g_is64 = (s_or[0] == 0) ? 1 : 0;
}

__device__ __forceinline__ int load_idx(const unsigned int* u32buf, long long elem, int is64, int n) {
    // elem = logical element index into the (2*E)-long edge_index array
    unsigned int v = is64 ? u32buf[2 * elem] : u32buf[elem];
    int iv = (int)v;
    return min(max(iv, 0), n - 1);
}

// ---------------- graph precompute ----------------
__global__ void k_init_deg(float* __restrict__ deg, int n) {
    int i = blockIdx.x * blockDim.x + threadIdx.x;
    if (i < n) deg[i] = 1.0f;   // self loop
}

__global__ void k_count_deg(const unsigned int* __restrict__ ei, float* __restrict__ deg,
                            int E, int n) {
    int e = blockIdx.x * blockDim.x + threadIdx.x;
    if (e < E) {
        int is64 = g_is64;
        int d = load_idx(ei, (long long)E + e, is64, n);
        atomicAdd(deg + d, 1.0f);
    }
}

__global__ void k_dinv(const float* __restrict__ deg, float* __restrict__ dinv, int n) {
    int i = blockIdx.x * blockDim.x + threadIdx.x;
    if (i < n) dinv[i] = rsqrtf(deg[i]);
}

__global__ void k_build_edges(const unsigned int* __restrict__ ei, const float* __restrict__ dinv,
                              int* __restrict__ src, int* __restrict__ dst,
                              float* __restrict__ norm, int E, int n) {
    int e = blockIdx.x * blockDim.x + threadIdx.x;
    if (e < E) {
        int is64 = g_is64;
        int s = load_idx(ei, e, is64, n);
        int d = load_idx(ei, (long long)E + e, is64, n);
        src[e] = s;
        dst[e] = d;
        norm[e] = dinv[s] * dinv[d];
    }
}

// ---------------- GEMM: out[n,64] = lrelu?(in[n,64]) @ W[64,64] ----------------
template <bool LRELU_IN>
__global__ __launch_bounds__(128)
void k_gemm64(const float* __restrict__ in, const float* __restrict__ W,
              float* __restrict__ out, int n) {
    __shared__ float Ws[64 * 64];
    for (int i = threadIdx.x; i < 64 * 16; i += blockDim.x)
        ((float4*)Ws)[i] = ((const float4*)W)[i];
    __syncthreads();

    int row = blockIdx.x * blockDim.x + threadIdx.x;
    if (row >= n) return;

    float acc[64];
#pragma unroll
    for (int j = 0; j < 64; j++) acc[j] = 0.f;

    const float4* inr = (const float4*)(in + (size_t)row * HID);

#pragma unroll 4
    for (int k4 = 0; k4 < 16; k4++) {
        float4 v = inr[k4];
        if (LRELU_IN) {
            v.x = lrelu1(v.x); v.y = lrelu1(v.y);
            v.z = lrelu1(v.z); v.w = lrelu1(v.w);
        }
        float av[4] = {v.x, v.y, v.z, v.w};
#pragma unroll
        for (int kk = 0; kk < 4; kk++) {
            const float* wrow = Ws + (k4 * 4 + kk) * 64;
#pragma unroll
            for (int j = 0; j < 64; j++)
                acc[j] = fmaf(av[kk], wrow[j], acc[j]);
        }
    }

    float4* outr = (float4*)(out + (size_t)row * HID);
#pragma unroll
    for (int j = 0; j < 16; j++)
        outr[j] = make_float4(acc[4 * j], acc[4 * j + 1], acc[4 * j + 2], acc[4 * j + 3]);
}

// ---------------- agg init: self-loop term + bias ----------------
__global__ void k_init_agg(const float* __restrict__ lin, const float* __restrict__ dinv,
                           const float* __restrict__ b, float* __restrict__ agg, int n) {
    int gid = blockIdx.x * blockDim.x + threadIdx.x;   // n*16 float4 slots
    if (gid >= n * 16) return;
    int node = gid >> 4;
    int c = gid & 15;
    float di = dinv[node];
    float w = di * di;
    float4 v = ((const float4*)lin)[gid];
    float4 bb = ((const float4*)b)[c];
    float4 o;
    o.x = fmaf(w, v.x, bb.x);
    o.y = fmaf(w, v.y, bb.y);
    o.z = fmaf(w, v.z, bb.z);
    o.w = fmaf(w, v.w, bb.w);
    ((float4*)agg)[gid] = o;
}

// ---------------- edge scatter: agg[dst] += norm * lin[src] ----------------
// One thread per (edge, feature); c contiguous within a warp => coalesced
// 128B gather from the source row and 32 contiguous atomics per warp.
__global__ __launch_bounds__(256)
void k_scatter(const float* __restrict__ lin, const int* __restrict__ src,
               const int* __restrict__ dst, const float* __restrict__ norm,
               float* __restrict__ agg, int E) {
    long long gid = (long long)blockIdx.x * blockDim.x + threadIdx.x;   // E*64 threads
    if (gid >= (long long)E * HID) return;
    int e = (int)(gid >> 6);
    int c = (int)(gid & 63);
    int s = __ldg(src + e);
    int d = __ldg(dst + e);
    float w = __ldg(norm + e);
    float v = __ldg(lin + (size_t)s * HID + c);
    atomicAdd(agg + (size_t)d * HID + c, w * v);
}

// ---------------- final leaky relu copy (plain stores to d_out) -----------
__global__ void k_lrelu_copy(const float* __restrict__ in, float* __restrict__ o, int n16) {
    int gid = blockIdx.x * blockDim.x + threadIdx.x;
    if (gid >= n16) return;
    float4 v = ((const float4*)in)[gid];
    v.x = lrelu1(v.x); v.y = lrelu1(v.y);
    v.z = lrelu1(v.z); v.w = lrelu1(v.w);
    ((float4*)o)[gid] = v;
}

// ---------------- launch ----------------
extern "C" void kernel_launch(void* const* d_in, const int* in_sizes, int n_in,
                              void* d_out, int out_size) {
    const float*        x  = (const float*)d_in[0];
    const unsigned int* ei = (const unsigned int*)d_in[1];
    const float*        W1 = (const float*)d_in[2];
    const float*        b1 = (const float*)d_in[3];
    const float*        W2 = (const float*)d_in[4];
    const float*        b2 = (const float*)d_in[5];
    const float*        W3 = (const float*)d_in[6];
    const float*        b3 = (const float*)d_in[7];
    float* out = (float*)d_out;

    const int n = in_sizes[0] / HID;        // 100000
    const int E = in_sizes[1] / 2;          // 1600000 (element count is dtype-agnostic)

    float* bufA;  cudaGetSymbolAddress((void**)&bufA, g_bufA);
    float* bufB;  cudaGetSymbolAddress((void**)&bufB, g_bufB);
    float* deg;   cudaGetSymbolAddress((void**)&deg,  g_deg);
    float* dinv;  cudaGetSymbolAddress((void**)&dinv, g_dinv);
    int*   src;   cudaGetSymbolAddress((void**)&src,  g_src);
    int*   dst;   cudaGetSymbolAddress((void**)&dst,  g_dst);
    float* norm;  cudaGetSymbolAddress((void**)&norm, g_norm);

    const int T = 256;
    int gn   = (n + T - 1) / T;
    int gE   = (E + T - 1) / T;
    int gn16 = (n * 16 + T - 1) / T;
    long long totalS = (long long)E * HID;
    int gS   = (int)((totalS + T - 1) / T);
    int gRow = (n + 127) / 128;

    // dtype detection + graph precompute
    k_detect<<<1, 256>>>(ei);
    k_init_deg<<<gn, T>>>(deg, n);
    k_count_deg<<<gE, T>>>(ei, deg, E, n);
    k_dinv<<<gn, T>>>(deg, dinv, n);
    k_build_edges<<<gE, T>>>(ei, dinv, src, dst, norm, E, n);

    // layer 1
    k_gemm64<false><<<gRow, 128>>>(x, W1, bufA, n);
    k_init_agg<<<gn16, T>>>(bufA, dinv, b1, bufB, n);
    k_scatter<<<gS, T>>>(bufA, src, dst, norm, bufB, E);

    // layer 2 (lrelu fused on GEMM input)
    k_gemm64<true><<<gRow, 128>>>(bufB, W2, bufA, n);
    k_init_agg<<<gn16, T>>>(bufA, dinv, b2, bufB, n);
    k_scatter<<<gS, T>>>(bufA, src, dst, norm, bufB, E);

    // layer 3 (aggregate in scratch, then lrelu-copy to d_out with plain stores)
    k_gemm64<true><<<gRow, 128>>>(bufB, W3, bufA, n);
    k_init_agg<<<gn16, T>>>(bufA, dinv, b3, bufB, n);
    k_scatter<<<gS, T>>>(bufA, src, dst, norm, bufB, E);
    k_lrelu_copy<<<gn16, T>>>(bufB, out, n * 16);
}

// round 4
// speedup vs baseline: 3.4385x; 3.4385x over previous
#include <cuda_runtime.h>
#include <stdint.h>

#define N_NODES 100000
#define E_EDGES 1600000
#define HID 64
#define SCAN_B 512

// ---------------- scratch (no allocation allowed) ----------------
__device__ float g_bufA[N_NODES * HID];        // h_lin (GEMM out)
__device__ float g_bufB[N_NODES * HID];        // layer output h
__device__ float g_dinv[N_NODES];
__device__ int   g_cnt[N_NODES];               // per-dst edge counts
__device__ int   g_off[N_NODES + 1];           // CSR offsets
__device__ int   g_cur[N_NODES];               // fill cursors
__device__ int   g_bsum[(N_NODES + SCAN_B - 1) / SCAN_B];
__device__ uint2 g_csr[E_EDGES];               // {src, norm_bits} sorted by dst
__device__ int   g_is64;                       // 1 if edge_index is int64

__device__ __forceinline__ float lrelu1(float v) {
    return fmaxf(v, 0.f) + 0.01f * fminf(v, 0.f);
}

// ---------------- dtype detection (unchanged from passing round) ----------
__global__ void k_detect(const unsigned int* __restrict__ u32buf) {
    __shared__ unsigned int s_or[256];
    unsigned int acc = 0;
    for (int i = threadIdx.x; i < 2048; i += 256)
        acc |= u32buf[2 * i + 1];          // hi word of candidate int64 #i
    s_or[threadIdx.x] = acc;
    __syncthreads();
    for (int s = 128; s > 0; s >>= 1) {
        if (threadIdx.x < s) s_or[threadIdx.x] |= s_or[threadIdx.x + s];
        __syncthreads();
    }
    if (threadIdx.x == 0) g_is64 = (s_or[0] == 0) ? 1 : 0;
}

__device__ __forceinline__ int load_idx(const unsigned int* u32buf, long long elem, int is64, int n) {
    unsigned int v = is64 ? u32buf[2 * elem] : u32buf[elem];
    int iv = (int)v;
    return min(max(iv, 0), n - 1);
}

// ---------------- graph precompute: counts, dinv ----------------
__global__ void k_zero2(int* __restrict__ cnt, int* __restrict__ cur, int n) {
    int i = blockIdx.x * blockDim.x + threadIdx.x;
    if (i < n) { cnt[i] = 0; cur[i] = 0; }
}

__global__ void k_count(const unsigned int* __restrict__ ei, int* __restrict__ cnt,
                        int E, int n) {
    int e = blockIdx.x * blockDim.x + threadIdx.x;
    if (e < E) {
        int is64 = g_is64;
        int d = load_idx(ei, (long long)E + e, is64, n);
        atomicAdd(cnt + d, 1);
    }
}

__global__ void k_dinv(const int* __restrict__ cnt, float* __restrict__ dinv, int n) {
    int i = blockIdx.x * blockDim.x + threadIdx.x;
    if (i < n) dinv[i] = rsqrtf(1.0f + (float)cnt[i]);   // +1 self loop
}

// ---------------- 3-kernel exclusive scan over cnt -> off ----------------
__global__ void k_scan_block(const int* __restrict__ cnt, int* __restrict__ off,
                             int* __restrict__ bsum, int n) {
    __shared__ int s[SCAN_B];
    int i = blockIdx.x * SCAN_B + threadIdx.x;
    int v = (i < n) ? cnt[i] : 0;
    s[threadIdx.x] = v;
    __syncthreads();
#pragma unroll
    for (int d = 1; d < SCAN_B; d <<= 1) {
        int t = (threadIdx.x >= d) ? s[threadIdx.x - d] : 0;
        __syncthreads();
        s[threadIdx.x] += t;
        __syncthreads();
    }
    if (i < n) off[i] = s[threadIdx.x] - v;            // exclusive within block
    if (threadIdx.x == SCAN_B - 1) bsum[blockIdx.x] = s[SCAN_B - 1];
}

__global__ void k_scan_bsum(int* __restrict__ bsum, int nb) {   // nb <= SCAN_B
    __shared__ int s[SCAN_B];
    int v = (threadIdx.x < nb) ? bsum[threadIdx.x] : 0;
    s[threadIdx.x] = v;
    __syncthreads();
#pragma unroll
    for (int d = 1; d < SCAN_B; d <<= 1) {
        int t = (threadIdx.x >= d) ? s[threadIdx.x - d] : 0;
        __syncthreads();
        s[threadIdx.x] += t;
        __syncthreads();
    }
    if (threadIdx.x < nb) bsum[threadIdx.x] = s[threadIdx.x] - v;   // exclusive
}

__global__ void k_scan_add(int* __restrict__ off, const int* __restrict__ bsum,
                           int n, int E) {
    int i = blockIdx.x * blockDim.x + threadIdx.x;
    if (i < n) off[i] += bsum[i / SCAN_B];
    if (i == 0) off[n] = E;
}

// ---------------- CSR fill ----------------
__global__ void k_fill(const unsigned int* __restrict__ ei, const float* __restrict__ dinv,
                       const int* __restrict__ off, int* __restrict__ cur,
                       uint2* __restrict__ csr, int E, int n) {
    int e = blockIdx.x * blockDim.x + threadIdx.x;
    if (e < E) {
        int is64 = g_is64;
        int s = load_idx(ei, e, is64, n);
        int d = load_idx(ei, (long long)E + e, is64, n);
        float nw = dinv[s] * dinv[d];
        int pos = off[d] + atomicAdd(cur + d, 1);
        csr[pos] = make_uint2((unsigned int)s, __float_as_uint(nw));
    }
}

// ---------------- GEMM: out[n,64] = in[n,64] @ W[64,64] ----------------
__global__ __launch_bounds__(128)
void k_gemm64(const float* __restrict__ in, const float* __restrict__ W,
              float* __restrict__ out, int n) {
    __shared__ float Ws[64 * 64];
    for (int i = threadIdx.x; i < 64 * 16; i += blockDim.x)
        ((float4*)Ws)[i] = ((const float4*)W)[i];
    __syncthreads();

    int row = blockIdx.x * blockDim.x + threadIdx.x;
    if (row >= n) return;

    float acc[64];
#pragma unroll
    for (int j = 0; j < 64; j++) acc[j] = 0.f;

    const float4* inr = (const float4*)(in + (size_t)row * HID);

#pragma unroll 4
    for (int k4 = 0; k4 < 16; k4++) {
        float4 v = inr[k4];
        float av[4] = {v.x, v.y, v.z, v.w};
#pragma unroll
        for (int kk = 0; kk < 4; kk++) {
            const float* wrow = Ws + (k4 * 4 + kk) * 64;
#pragma unroll
            for (int j = 0; j < 64; j++)
                acc[j] = fmaf(av[kk], wrow[j], acc[j]);
        }
    }

    float4* outr = (float4*)(out + (size_t)row * HID);
#pragma unroll
    for (int j = 0; j < 16; j++)
        outr[j] = make_float4(acc[4 * j], acc[4 * j + 1], acc[4 * j + 2], acc[4 * j + 3]);
}

// ---------------- CSR gather: h[node] = lrelu(bias + dinv^2*lin[node]
//                                 + sum_e norm_e * lin[src_e]) ----------------
// One warp per destination node; lane owns 2 feature columns (float2).
__global__ __launch_bounds__(256)
void k_gather(const float* __restrict__ lin, const uint2* __restrict__ csr,
              const int* __restrict__ off, const float* __restrict__ dinv,
              const float* __restrict__ bias, float* __restrict__ outp, int n) {
    int warp = (blockIdx.x * blockDim.x + threadIdx.x) >> 5;
    int lane = threadIdx.x & 31;
    if (warp >= n) return;
    int node = warp;

    int beg = __ldg(off + node);
    int end = __ldg(off + node + 1);
    float di = __ldg(dinv + node);
    float w = di * di;

    const float2* lin2 = (const float2*)lin;
    float2 v = __ldg(lin2 + (size_t)node * 32 + lane);
    float2 b = __ldg(((const float2*)bias) + lane);
    float ax = fmaf(w, v.x, b.x);
    float ay = fmaf(w, v.y, b.y);

    int i = beg;
    for (; i + 2 <= end; i += 2) {
        uint2 e0 = __ldg(csr + i);
        uint2 e1 = __ldg(csr + i + 1);
        float2 s0 = __ldg(lin2 + (size_t)e0.x * 32 + lane);
        float2 s1 = __ldg(lin2 + (size_t)e1.x * 32 + lane);
        float w0 = __uint_as_float(e0.y);
        float w1 = __uint_as_float(e1.y);
        ax = fmaf(w0, s0.x, ax); ay = fmaf(w0, s0.y, ay);
        ax = fmaf(w1, s1.x, ax); ay = fmaf(w1, s1.y, ay);
    }
    if (i < end) {
        uint2 e0 = __ldg(csr + i);
        float2 s0 = __ldg(lin2 + (size_t)e0.x * 32 + lane);
        float w0 = __uint_as_float(e0.y);
        ax = fmaf(w0, s0.x, ax); ay = fmaf(w0, s0.y, ay);
    }

    float2 o;
    o.x = lrelu1(ax);
    o.y = lrelu1(ay);
    ((float2*)outp)[(size_t)node * 32 + lane] = o;
}

// ---------------- launch ----------------
extern "C" void kernel_launch(void* const* d_in, const int* in_sizes, int n_in,
                              void* d_out, int out_size) {
    const float*        x  = (const float*)d_in[0];
    const unsigned int* ei = (const unsigned int*)d_in[1];
    const float*        W1 = (const float*)d_in[2];
    const float*        b1 = (const float*)d_in[3];
    const float*        W2 = (const float*)d_in[4];
    const float*        b2 = (const float*)d_in[5];
    const float*        W3 = (const float*)d_in[6];
    const float*        b3 = (const float*)d_in[7];
    float* out = (float*)d_out;

    const int n = in_sizes[0] / HID;        // 100000
    const int E = in_sizes[1] / 2;          // 1600000

    float* bufA;  cudaGetSymbolAddress((void**)&bufA, g_bufA);
    float* bufB;  cudaGetSymbolAddress((void**)&bufB, g_bufB);
    float* dinv;  cudaGetSymbolAddress((void**)&dinv, g_dinv);
    int*   cnt;   cudaGetSymbolAddress((void**)&cnt,  g_cnt);
    int*   off;   cudaGetSymbolAddress((void**)&off,  g_off);
    int*   cur;   cudaGetSymbolAddress((void**)&cur,  g_cur);
    int*   bsum;  cudaGetSymbolAddress((void**)&bsum, g_bsum);
    uint2* csr;   cudaGetSymbolAddress((void**)&csr,  g_csr);

    const int T = 256;
    int gn  = (n + T - 1) / T;
    int gE  = (E + T - 1) / T;
    int nb  = (n + SCAN_B - 1) / SCAN_B;     // 196
    int gRow = (n + 127) / 128;
    int gGat = (n * 32 + T - 1) / T;         // warp per node

    // dtype detection + CSR build
    k_detect<<<1, 256>>>(ei);
    k_zero2<<<gn, T>>>(cnt, cur, n);
    k_count<<<gE, T>>>(ei, cnt, E, n);
    k_dinv<<<gn, T>>>(cnt, dinv, n);
    k_scan_block<<<nb, SCAN_B>>>(cnt, off, bsum, n);
    k_scan_bsum<<<1, SCAN_B>>>(bsum, nb);
    k_scan_add<<<gn, T>>>(off, bsum, n, E);
    k_fill<<<gE, T>>>(ei, dinv, off, cur, csr, E, n);

    // layer 1
    k_gemm64<<<gRow, 128>>>(x, W1, bufA, n);
    k_gather<<<gGat, T>>>(bufA, csr, off, dinv, b1, bufB, n);
    // layer 2
    k_gemm64<<<gRow, 128>>>(bufB, W2, bufA, n);
    k_gather<<<gGat, T>>>(bufA, csr, off, dinv, b2, bufB, n);
    // layer 3 -> d_out directly (plain stores only)
    k_gemm64<<<gRow, 128>>>(bufB, W3, bufA, n);
    k_gather<<<gGat, T>>>(bufA, csr, off, dinv, b3, out, n);
}